// round 8
// baseline (speedup 1.0000x reference)
#include <cuda_runtime.h>
#include <cstdint>

// ---------------- problem constants ----------------
#define D_DIM    64
#define SUBN     256
#define T_LEN    16384
#define N_ROWS   262144
#define ZQ_ELEMS 16777216
#define LOSS_OFF ZQ_ELEMS
#define PERP_OFF (ZQ_ELEMS + 1)
#define IDX_OFF  (ZQ_ELEMS + 2)
#define TILE_M   128
#define NTILES   (N_ROWS / TILE_M)   // 2048
#define ESTR     68                  // padded row stride (floats)
#define MARGIN   1.2e-4f             // near-tie rescue window (>=15x max approx err)

// ---------------- persistent scratch ----------------
// Invariant: zero at kernel_launch entry; vq_finalize re-zeros after reading.
__device__ int    g_counts[SUBN];
__device__ double g_sse;

// ---------------- smem layout ----------------------
struct Smem {
    uint32_t B1[SUBN * ESTR];            // tf32 limb1 of E, [n][k]
    uint32_t B2[SUBN * ESTR];            // tf32 limb2 of E
    float    zt[TILE_M * ESTR];          // fp32 z tile
    float    szz[TILE_M];                // ||z||^2 per row (R1-exact)
    float    ee[SUBN];                   // ||e||^2 (R1-exact)
    unsigned long long cand[TILE_M][8];  // per-(row, warp) approx best
    unsigned long long rbest[TILE_M];    // exact-rescored best (atomicMin)
    float    thr[TILE_M];                // rescue threshold per row
    int      sidx[TILE_M];
    int      shist[SUBN];
    float    sred[8];
};
#define SMEM_TOT ((int)sizeof(Smem))

// ---------------- helpers --------------------------
__device__ __forceinline__ unsigned long long ffma2(unsigned long long a,
                                                    unsigned long long b,
                                                    unsigned long long c) {
    unsigned long long d;
    asm("fma.rn.f32x2 %0, %1, %2, %3;" : "=l"(d) : "l"(a), "l"(b), "l"(c));
    return d;
}
__device__ __forceinline__ float2 unpack2(unsigned long long v) {
    float2 r;
    asm("mov.b64 {%0, %1}, %2;" : "=f"(r.x), "=f"(r.y) : "l"(v));
    return r;
}
// 2-way exact tf32 split: v = limb1 + limb2 + O(2^-22 v)
__device__ __forceinline__ void split_tf32(float v, uint32_t& h1, uint32_t& h2) {
    asm("cvt.rna.tf32.f32 %0, %1;" : "=r"(h1) : "f"(v));
    float r = v - __uint_as_float(h1);   // exact
    asm("cvt.rna.tf32.f32 %0, %1;" : "=r"(h2) : "f"(r));
}
// m16n8k8 tf32 MMA, D += A*B
__device__ __forceinline__ void mma_tf32(float* c, const uint32_t* a,
                                         const uint32_t* b) {
    asm volatile(
        "mma.sync.aligned.m16n8k8.row.col.f32.tf32.tf32.f32 "
        "{%0,%1,%2,%3}, {%4,%5,%6,%7}, {%8,%9}, {%0,%1,%2,%3};"
        : "+f"(c[0]), "+f"(c[1]), "+f"(c[2]), "+f"(c[3])
        : "r"(a[0]), "r"(a[1]), "r"(a[2]), "r"(a[3]), "r"(b[0]), "r"(b[1]));
}
__device__ __forceinline__ unsigned long long packdj(float d, int j) {
    return ((unsigned long long)__float_as_uint(d) << 32) | (unsigned)j;
}
// R1's exact fp32 distance chain: packed ffma2 dot, then (zz+ee) - 2*dot
__device__ __forceinline__ float exact_d(const float* zrow, const float* erow,
                                         float zz, float eej) {
    const ulonglong2* zp = (const ulonglong2*)zrow;
    const ulonglong2* ep = (const ulonglong2*)erow;
    unsigned long long a0 = 0ull, a1 = 0ull;
    #pragma unroll
    for (int i = 0; i < 16; i++) {
        ulonglong2 zv = zp[i];
        ulonglong2 ev = ep[i];
        a0 = ffma2(zv.x, ev.x, a0);
        a1 = ffma2(zv.y, ev.y, a1);
    }
    float2 x0 = unpack2(a0), x1 = unpack2(a1);
    const float dot = (x0.x + x0.y) + (x1.x + x1.y);
    return (zz + eej) - 2.0f * dot;
}

// ==================================================================
__global__ __launch_bounds__(256, 1) void vq_mma(const float* __restrict__ z,
                                                 const float* __restrict__ one_hot,
                                                 const float* __restrict__ W,
                                                 float* __restrict__ out) {
    extern __shared__ char smem_raw[];
    Smem* S = (Smem*)smem_raw;

    const int tid  = threadIdx.x;
    const int lane = tid & 31;
    const int w    = tid >> 5;
    const int lg   = lane >> 2;     // 0..7
    const int lk   = lane & 3;      // 0..3
    const int wN   = w * 32;        // warp's 32-col slice of N=256

    // pos = argmax(one_hot), first-max semantics
    float mv = one_hot[0];
    int pos = 0;
    #pragma unroll
    for (int i = 1; i < 7; i++) {
        float v = one_hot[i];
        if (v > mv) { mv = v; pos = i; }
    }
    const float* Wp = W + (size_t)pos * SUBN * D_DIM;

    // ---- E prep: thread j; ee exact R1 order; tf32 limb tiles ----
    {
        const float4* er4 = (const float4*)(Wp + (size_t)tid * D_DIM);
        float4 buf[16];
        #pragma unroll
        for (int i = 0; i < 16; i++) buf[i] = er4[i];
        float s = 0.f;
        #pragma unroll
        for (int i = 0; i < 16; i++) {
            s = fmaf(buf[i].x, buf[i].x, s);
            s = fmaf(buf[i].y, buf[i].y, s);
            s = fmaf(buf[i].z, buf[i].z, s);
            s = fmaf(buf[i].w, buf[i].w, s);
        }
        S->ee[tid] = s;
        #pragma unroll
        for (int i = 0; i < 16; i++) {
            float f[4] = {buf[i].x, buf[i].y, buf[i].z, buf[i].w};
            #pragma unroll
            for (int q = 0; q < 4; q++) {
                uint32_t h1, h2;
                split_tf32(f[q], h1, h2);
                S->B1[tid * ESTR + i * 4 + q] = h1;
                S->B2[tid * ESTR + i * 4 + q] = h2;
            }
        }
        S->shist[tid] = 0;
    }
    __syncthreads();

    float sse_loc = 0.f;

    for (int tile = blockIdx.x; tile < NTILES; tile += gridDim.x) {
        const int m0 = tile * TILE_M;

        // ---- load z tile (thread = (row, half)) ----
        {
            const int m = tid >> 1, h = tid & 1;
            const float4* src =
                (const float4*)(z + (size_t)(m0 + m) * D_DIM + h * 32);
            float4* dst = (float4*)(S->zt + m * ESTR + h * 32);
            #pragma unroll
            for (int i = 0; i < 8; i++) dst[i] = src[i];
        }
        __syncthreads();

        // ---- zz per row, bit-identical to R1 chain ----
        if (tid < TILE_M) {
            const ulonglong2* zp = (const ulonglong2*)(S->zt + tid * ESTR);
            unsigned long long zzacc = 0ull;
            #pragma unroll
            for (int i = 0; i < 16; i++) {
                ulonglong2 v = zp[i];
                zzacc = ffma2(v.x, v.x, zzacc);
                zzacc = ffma2(v.y, v.y, zzacc);
            }
            float2 p = unpack2(zzacc);
            S->szz[tid] = p.x + p.y;
        }
        __syncthreads();

        // ---- GEMM: dot[m][n] = z . e, 3 tf32 limb products ----
        float acc[8][4][4];
        #pragma unroll
        for (int mi = 0; mi < 8; mi++)
            #pragma unroll
            for (int ni = 0; ni < 4; ni++)
                #pragma unroll
                for (int q = 0; q < 4; q++) acc[mi][ni][q] = 0.f;

        #pragma unroll 1
        for (int k8 = 0; k8 < 8; k8++) {
            const int kb = k8 * 8;
            uint32_t b1f[4][2], b2f[4][2];
            #pragma unroll
            for (int ni = 0; ni < 4; ni++) {
                const int nrow = wN + ni * 8 + lg;
                const uint32_t* p1 = S->B1 + nrow * ESTR + kb + lk;
                const uint32_t* p2 = S->B2 + nrow * ESTR + kb + lk;
                b1f[ni][0] = p1[0]; b1f[ni][1] = p1[4];
                b2f[ni][0] = p2[0]; b2f[ni][1] = p2[4];
            }
            #pragma unroll
            for (int mi = 0; mi < 8; mi++) {
                const int r = mi * 16 + lg;
                const float* z0 = S->zt + r * ESTR + kb + lk;
                const float* z1 = S->zt + (r + 8) * ESTR + kb + lk;
                uint32_t a1[4], a2[4];
                split_tf32(z0[0], a1[0], a2[0]);
                split_tf32(z1[0], a1[1], a2[1]);
                split_tf32(z0[4], a1[2], a2[2]);
                split_tf32(z1[4], a1[3], a2[3]);
                #pragma unroll
                for (int ni = 0; ni < 4; ni++) {
                    mma_tf32(acc[mi][ni], a1, b1f[ni]);   // z1*e1
                    mma_tf32(acc[mi][ni], a2, b1f[ni]);   // z2*e1
                    mma_tf32(acc[mi][ni], a1, b2f[ni]);   // z1*e2
                }
            }
        }

        // ---- stage 1: approximate per-(row,warp) argmin ----
        // c0:(r, 2lk) c1:(r, 2lk+1) c2:(r+8, 2lk) c3:(r+8, 2lk+1)
        #pragma unroll
        for (int mi = 0; mi < 8; mi++) {
            unsigned long long blo = ~0ull, bhi = ~0ull;
            const int rlo = mi * 16 + lg;
            const float zzlo = S->szz[rlo];
            const float zzhi = S->szz[rlo + 8];
            #pragma unroll
            for (int ni = 0; ni < 4; ni++) {
                const int j0 = wN + ni * 8 + lk * 2;
                const float e0 = S->ee[j0];
                const float e1 = S->ee[j0 + 1];
                const float d00 = (zzlo + e0) - 2.0f * acc[mi][ni][0];
                const float d01 = (zzlo + e1) - 2.0f * acc[mi][ni][1];
                const float d10 = (zzhi + e0) - 2.0f * acc[mi][ni][2];
                const float d11 = (zzhi + e1) - 2.0f * acc[mi][ni][3];
                unsigned long long p;
                p = packdj(d00, j0);     if (p < blo) blo = p;
                p = packdj(d01, j0 + 1); if (p < blo) blo = p;
                p = packdj(d10, j0);     if (p < bhi) bhi = p;
                p = packdj(d11, j0 + 1); if (p < bhi) bhi = p;
            }
            #pragma unroll
            for (int s = 1; s <= 2; s <<= 1) {
                unsigned long long o;
                o = __shfl_xor_sync(0xffffffffu, blo, s); if (o < blo) blo = o;
                o = __shfl_xor_sync(0xffffffffu, bhi, s); if (o < bhi) bhi = o;
            }
            if (lk == 0) {
                S->cand[rlo][w]     = blo;
                S->cand[rlo + 8][w] = bhi;
            }
        }
        __syncthreads();

        // ---- per-row approx best -> rescue threshold ----
        if (tid < TILE_M) {
            unsigned long long m = S->cand[tid][0];
            #pragma unroll
            for (int w2 = 1; w2 < 8; w2++) {
                unsigned long long o = S->cand[tid][w2];
                if (o < m) m = o;
            }
            S->thr[tid]   = __uint_as_float((uint32_t)(m >> 32)) + MARGIN;
            S->rbest[tid] = ~0ull;
        }
        __syncthreads();

        // ---- stage 2: rescan; rescue near-ties with exact R1 chain ----
        #pragma unroll
        for (int mi = 0; mi < 8; mi++) {
            const int rlo = mi * 16 + lg;
            const int rhi = rlo + 8;
            const float zzlo = S->szz[rlo];
            const float zzhi = S->szz[rhi];
            const float tlo = S->thr[rlo];
            const float thi = S->thr[rhi];
            #pragma unroll
            for (int ni = 0; ni < 4; ni++) {
                const int j0 = wN + ni * 8 + lk * 2;
                const float e0 = S->ee[j0];
                const float e1 = S->ee[j0 + 1];
                const float d00 = (zzlo + e0) - 2.0f * acc[mi][ni][0];
                const float d01 = (zzlo + e1) - 2.0f * acc[mi][ni][1];
                const float d10 = (zzhi + e0) - 2.0f * acc[mi][ni][2];
                const float d11 = (zzhi + e1) - 2.0f * acc[mi][ni][3];
                if (d00 <= tlo) {
                    float de = exact_d(S->zt + rlo * ESTR, Wp + (size_t)j0 * D_DIM, zzlo, e0);
                    atomicMin(&S->rbest[rlo], packdj(de, j0));
                }
                if (d01 <= tlo) {
                    float de = exact_d(S->zt + rlo * ESTR, Wp + (size_t)(j0 + 1) * D_DIM, zzlo, e1);
                    atomicMin(&S->rbest[rlo], packdj(de, j0 + 1));
                }
                if (d10 <= thi) {
                    float de = exact_d(S->zt + rhi * ESTR, Wp + (size_t)j0 * D_DIM, zzhi, e0);
                    atomicMin(&S->rbest[rhi], packdj(de, j0));
                }
                if (d11 <= thi) {
                    float de = exact_d(S->zt + rhi * ESTR, Wp + (size_t)(j0 + 1) * D_DIM, zzhi, e1);
                    atomicMin(&S->rbest[rhi], packdj(de, j0 + 1));
                }
            }
        }
        __syncthreads();

        // ---- commit: exact winner per row ----
        if (tid < TILE_M) {
            const unsigned long long m = S->rbest[tid];
            const int j = (int)(m & 0xffffffffu);
            const float sc = __uint_as_float((uint32_t)(m >> 32));
            S->sidx[tid] = j;
            atomicAdd(&S->shist[j], 1);
            sse_loc += sc;                       // exact ||z - e||^2 (R1 chain)
            out[IDX_OFF + m0 + tid] = (float)j;
        }
        __syncthreads();

        // ---- z_q transposed write (coalesced over t) ----
        {
            const int t = tid & 127, dh = tid >> 7;
            const int n = m0 + t;
            const int b = n >> 14, tt = n & (T_LEN - 1);
            const int j = S->sidx[t];
            const float* er = Wp + (size_t)j * D_DIM;
            float* ob = out + (size_t)b * D_DIM * T_LEN + tt;
            #pragma unroll
            for (int d0 = dh; d0 < D_DIM; d0 += 2)
                ob[(size_t)d0 * T_LEN] = er[d0];
        }
        __syncthreads();
    }

    // ---- block reductions ----
    float s = sse_loc;
    #pragma unroll
    for (int o = 16; o > 0; o >>= 1)
        s += __shfl_down_sync(0xffffffffu, s, o);
    if ((tid & 31) == 0) S->sred[tid >> 5] = s;
    __syncthreads();
    if (tid == 0) {
        float tot = 0.f;
        #pragma unroll
        for (int q = 0; q < 8; q++) tot += S->sred[q];
        atomicAdd(&g_sse, (double)tot);
    }
    atomicAdd(&g_counts[tid], S->shist[tid]);
}

// ------------------------------------------------------------------
__global__ void vq_finalize(float* __restrict__ out) {
    __shared__ float sw[8];
    int tid = threadIdx.x;          // 256 threads
    float c = (float)g_counts[tid];
    g_counts[tid] = 0;              // restore zero-invariant for replay
    float em = c * (1.0f / 262144.0f);
    float v = em * logf(em + 1e-10f);
    #pragma unroll
    for (int o = 16; o > 0; o >>= 1)
        v += __shfl_down_sync(0xffffffffu, v, o);
    if ((tid & 31) == 0) sw[tid >> 5] = v;
    __syncthreads();
    if (tid == 0) {
        float H = 0.f;
        #pragma unroll
        for (int q = 0; q < 8; q++) H += sw[q];
        out[PERP_OFF] = expf(-H);
        double sse = g_sse;
        g_sse = 0.0;                // restore zero-invariant
        float m = (float)(sse * (1.0 / 16777216.0));
        out[LOSS_OFF] = 0.25f * m + m;   // BETA*mse + mse
    }
}

// ------------------------------------------------------------------
extern "C" void kernel_launch(void* const* d_in, const int* in_sizes, int n_in,
                              void* d_out, int out_size) {
    const float* z       = (const float*)d_in[0];
    const float* one_hot = (const float*)d_in[1];
    const float* W       = (const float*)d_in[2];
    float* out           = (float*)d_out;

    int nsm = 148;
    cudaDeviceGetAttribute(&nsm, cudaDevAttrMultiProcessorCount, 0);
    if (nsm <= 0) nsm = 148;

    cudaFuncSetAttribute(vq_mma, cudaFuncAttributeMaxDynamicSharedMemorySize,
                         SMEM_TOT);
    vq_mma<<<nsm, 256, SMEM_TOT>>>(z, one_hot, W, out);
    vq_finalize<<<1, 256>>>(out);
}

// round 10
// speedup vs baseline: 1.1343x; 1.1343x over previous
#include <cuda_runtime.h>
#include <cuda_fp16.h>
#include <cstdint>

// ---------------- problem constants ----------------
#define D_DIM    64
#define SUBN     256
#define T_LEN    16384
#define N_ROWS   262144
#define ZQ_ELEMS 16777216
#define LOSS_OFF ZQ_ELEMS
#define PERP_OFF (ZQ_ELEMS + 1)
#define IDX_OFF  (ZQ_ELEMS + 2)
#define TILE_M   128
#define NTILES   (N_ROWS / TILE_M)   // 2048
#define ESTR     68                  // fp32 z row stride (floats)
#define HSTR     36                  // half2 (u32) row stride, bank-conflict-free
#define MARGIN   1.2e-4f             // near-tie rescue window (~600x approx err)
#define ESCALE   1024.0f             // E pre-scale (exact power of 2)
#define DSCALE   0.001953125f        // 2/1024, folds the 2x and the descale

// ---------------- persistent scratch ----------------
// Invariant: zero at kernel_launch entry; vq_finalize re-zeros after reading.
__device__ int    g_counts[SUBN];
__device__ double g_sse;

// ---------------- smem layout ----------------------
struct Smem {
    uint32_t B1[SUBN * HSTR];            // fp16 limb1 of E*1024, half2 [n][kk]
    uint32_t B2[SUBN * HSTR];            // fp16 limb2 of E*1024
    uint32_t A1[TILE_M * HSTR];          // fp16 limb1 of z
    uint32_t A2[TILE_M * HSTR];          // fp16 limb2 of z
    float    zt[TILE_M * ESTR];          // fp32 z tile (exact rescue)
    float    szz[TILE_M];                // ||z||^2 per row (R1-exact)
    float    ee[SUBN];                   // ||e||^2 (R1-exact)
    unsigned long long cand[TILE_M][8];  // per-(row, warp) approx best
    unsigned long long rbest[TILE_M];    // exact-rescored best (atomicMin)
    float    thr[TILE_M];                // rescue threshold per row
    int      sidx[TILE_M];
    int      shist[SUBN];
    float    sred[8];
};
#define SMEM_TOT ((int)sizeof(Smem))

// ---------------- helpers --------------------------
__device__ __forceinline__ uint32_t pack_h2(__half lo, __half hi) {
    return (uint32_t)__half_as_ushort(lo) |
           ((uint32_t)__half_as_ushort(hi) << 16);
}
__device__ __forceinline__ unsigned long long ffma2(unsigned long long a,
                                                    unsigned long long b,
                                                    unsigned long long c) {
    unsigned long long d;
    asm("fma.rn.f32x2 %0, %1, %2, %3;" : "=l"(d) : "l"(a), "l"(b), "l"(c));
    return d;
}
__device__ __forceinline__ float2 unpack2(unsigned long long v) {
    float2 r;
    asm("mov.b64 {%0, %1}, %2;" : "=f"(r.x), "=f"(r.y) : "l"(v));
    return r;
}
// 2-way fp16 split: v = h1 + h2 + O(2^-22 v); residual subtraction exact
__device__ __forceinline__ void split_f16(float v, __half& h1, __half& h2) {
    h1 = __float2half_rn(v);
    float r = v - __half2float(h1);
    h2 = __float2half_rn(r);
}
// m16n8k16 fp16 MMA, fp32 accumulate, D += A*B  (legacy HMMA path)
__device__ __forceinline__ void mma_f16(float* c, const uint32_t* a,
                                        const uint32_t* b) {
    asm volatile(
        "mma.sync.aligned.m16n8k16.row.col.f32.f16.f16.f32 "
        "{%0,%1,%2,%3}, {%4,%5,%6,%7}, {%8,%9}, {%0,%1,%2,%3};"
        : "+f"(c[0]), "+f"(c[1]), "+f"(c[2]), "+f"(c[3])
        : "r"(a[0]), "r"(a[1]), "r"(a[2]), "r"(a[3]), "r"(b[0]), "r"(b[1]));
}
__device__ __forceinline__ unsigned long long packdj(float d, int j) {
    return ((unsigned long long)__float_as_uint(d) << 32) | (unsigned)j;
}
// R1's exact fp32 distance chain: packed ffma2 dot, then (zz+ee) - 2*dot
__device__ __forceinline__ float exact_d(const float* zrow, const float* erow,
                                         float zz, float eej) {
    const ulonglong2* zp = (const ulonglong2*)zrow;
    const ulonglong2* ep = (const ulonglong2*)erow;
    unsigned long long a0 = 0ull, a1 = 0ull;
    #pragma unroll
    for (int i = 0; i < 16; i++) {
        ulonglong2 zv = zp[i];
        ulonglong2 ev = ep[i];
        a0 = ffma2(zv.x, ev.x, a0);
        a1 = ffma2(zv.y, ev.y, a1);
    }
    float2 x0 = unpack2(a0), x1 = unpack2(a1);
    const float dot = (x0.x + x0.y) + (x1.x + x1.y);
    return (zz + eej) - 2.0f * dot;
}

// ==================================================================
__global__ __launch_bounds__(256, 1) void vq_mma(const float* __restrict__ z,
                                                 const float* __restrict__ one_hot,
                                                 const float* __restrict__ W,
                                                 float* __restrict__ out) {
    extern __shared__ char smem_raw[];
    Smem* S = (Smem*)smem_raw;

    const int tid  = threadIdx.x;
    const int lane = tid & 31;
    const int w    = tid >> 5;
    const int lg   = lane >> 2;     // groupID 0..7
    const int lk   = lane & 3;      // threadID-in-group 0..3
    const int wN   = w * 32;        // warp's 32-col slice of N=256

    // pos = argmax(one_hot), first-max semantics
    float mv = one_hot[0];
    int pos = 0;
    #pragma unroll
    for (int i = 1; i < 7; i++) {
        float v = one_hot[i];
        if (v > mv) { mv = v; pos = i; }
    }
    const float* Wp = W + (size_t)pos * SUBN * D_DIM;

    // ---- E prep: thread j; ee exact R1 order; fp16 limb tiles (scaled) ----
    {
        const float4* er4 = (const float4*)(Wp + (size_t)tid * D_DIM);
        float4 buf[16];
        #pragma unroll
        for (int i = 0; i < 16; i++) buf[i] = er4[i];
        float s = 0.f;
        #pragma unroll
        for (int i = 0; i < 16; i++) {
            s = fmaf(buf[i].x, buf[i].x, s);
            s = fmaf(buf[i].y, buf[i].y, s);
            s = fmaf(buf[i].z, buf[i].z, s);
            s = fmaf(buf[i].w, buf[i].w, s);
        }
        S->ee[tid] = s;
        #pragma unroll
        for (int i = 0; i < 16; i++) {
            float f[4] = {buf[i].x, buf[i].y, buf[i].z, buf[i].w};
            #pragma unroll
            for (int p = 0; p < 2; p++) {          // 2 half2 per float4
                __half a1, a2, b1, b2;
                split_f16(f[2 * p] * ESCALE,     a1, a2);
                split_f16(f[2 * p + 1] * ESCALE, b1, b2);
                const int kk = i * 2 + p;
                S->B1[tid * HSTR + kk] = pack_h2(a1, b1);
                S->B2[tid * HSTR + kk] = pack_h2(a2, b2);
            }
        }
        S->shist[tid] = 0;
    }
    __syncthreads();

    float sse_loc = 0.f;

    for (int tile = blockIdx.x; tile < NTILES; tile += gridDim.x) {
        const int m0 = tile * TILE_M;

        // ---- load z half-row: fp32 stash + fp16 limb tiles ----
        {
            const int m = tid >> 1, h = tid & 1;
            const float4* src =
                (const float4*)(z + (size_t)(m0 + m) * D_DIM + h * 32);
            float4 v[8];
            #pragma unroll
            for (int i = 0; i < 8; i++) v[i] = src[i];
            float4* dst = (float4*)(S->zt + m * ESTR + h * 32);
            #pragma unroll
            for (int i = 0; i < 8; i++) dst[i] = v[i];
            #pragma unroll
            for (int i = 0; i < 8; i++) {
                float f[4] = {v[i].x, v[i].y, v[i].z, v[i].w};
                #pragma unroll
                for (int p = 0; p < 2; p++) {
                    __half a1, a2, b1, b2;
                    split_f16(f[2 * p],     a1, a2);
                    split_f16(f[2 * p + 1], b1, b2);
                    const int kk = h * 16 + i * 2 + p;
                    S->A1[m * HSTR + kk] = pack_h2(a1, b1);
                    S->A2[m * HSTR + kk] = pack_h2(a2, b2);
                }
            }
        }
        __syncthreads();

        // ---- zz per row, bit-identical to R1 chain ----
        if (tid < TILE_M) {
            const ulonglong2* zp = (const ulonglong2*)(S->zt + tid * ESTR);
            unsigned long long zzacc = 0ull;
            #pragma unroll
            for (int i = 0; i < 16; i++) {
                ulonglong2 v = zp[i];
                zzacc = ffma2(v.x, v.x, zzacc);
                zzacc = ffma2(v.y, v.y, zzacc);
            }
            float2 p = unpack2(zzacc);
            S->szz[tid] = p.x + p.y;
        }
        __syncthreads();

        // ---- GEMM: 1024*dot[m][n], 3 fp16 limb products (z1e1+z2e1+z1e2) ----
        float acc[8][4][4];
        #pragma unroll
        for (int mi = 0; mi < 8; mi++)
            #pragma unroll
            for (int ni = 0; ni < 4; ni++)
                #pragma unroll
                for (int q = 0; q < 4; q++) acc[mi][ni][q] = 0.f;

        #pragma unroll
        for (int k16 = 0; k16 < 4; k16++) {
            const int kb = k16 * 8;                 // u32 kk base
            // B fragments: b0:(k=2lk, n=lg) b1:(k=2lk+8, n=lg)
            uint32_t b1f[4][2], b2f[4][2];
            #pragma unroll
            for (int ni = 0; ni < 4; ni++) {
                const int n = wN + ni * 8 + lg;
                b1f[ni][0] = S->B1[n * HSTR + kb + lk];
                b1f[ni][1] = S->B1[n * HSTR + kb + lk + 4];
                b2f[ni][0] = S->B2[n * HSTR + kb + lk];
                b2f[ni][1] = S->B2[n * HSTR + kb + lk + 4];
            }
            #pragma unroll
            for (int mi = 0; mi < 8; mi++) {
                const int rlo = (mi * 16 + lg) * HSTR;
                const int rhi = (mi * 16 + 8 + lg) * HSTR;
                uint32_t a1f[4], a2f[4];
                a1f[0] = S->A1[rlo + kb + lk];
                a1f[1] = S->A1[rhi + kb + lk];
                a1f[2] = S->A1[rlo + kb + lk + 4];
                a1f[3] = S->A1[rhi + kb + lk + 4];
                a2f[0] = S->A2[rlo + kb + lk];
                a2f[1] = S->A2[rhi + kb + lk];
                a2f[2] = S->A2[rlo + kb + lk + 4];
                a2f[3] = S->A2[rhi + kb + lk + 4];
                #pragma unroll
                for (int ni = 0; ni < 4; ni++) {
                    mma_f16(acc[mi][ni], a1f, b1f[ni]);   // z1*e1
                    mma_f16(acc[mi][ni], a2f, b1f[ni]);   // z2*e1
                    mma_f16(acc[mi][ni], a1f, b2f[ni]);   // z1*e2
                }
            }
        }

        // ---- stage 1: approximate per-(row,warp) argmin ----
        // c0:(r, 2lk) c1:(r, 2lk+1) c2:(r+8, 2lk) c3:(r+8, 2lk+1)
        #pragma unroll
        for (int mi = 0; mi < 8; mi++) {
            unsigned long long blo = ~0ull, bhi = ~0ull;
            const int rlo = mi * 16 + lg;
            const float zzlo = S->szz[rlo];
            const float zzhi = S->szz[rlo + 8];
            #pragma unroll
            for (int ni = 0; ni < 4; ni++) {
                const int j0 = wN + ni * 8 + lk * 2;
                const float e0 = S->ee[j0];
                const float e1 = S->ee[j0 + 1];
                const float d00 = fmaf(acc[mi][ni][0], -DSCALE, zzlo + e0);
                const float d01 = fmaf(acc[mi][ni][1], -DSCALE, zzlo + e1);
                const float d10 = fmaf(acc[mi][ni][2], -DSCALE, zzhi + e0);
                const float d11 = fmaf(acc[mi][ni][3], -DSCALE, zzhi + e1);
                unsigned long long p;
                p = packdj(d00, j0);     if (p < blo) blo = p;
                p = packdj(d01, j0 + 1); if (p < blo) blo = p;
                p = packdj(d10, j0);     if (p < bhi) bhi = p;
                p = packdj(d11, j0 + 1); if (p < bhi) bhi = p;
            }
            #pragma unroll
            for (int s = 1; s <= 2; s <<= 1) {
                unsigned long long o;
                o = __shfl_xor_sync(0xffffffffu, blo, s); if (o < blo) blo = o;
                o = __shfl_xor_sync(0xffffffffu, bhi, s); if (o < bhi) bhi = o;
            }
            if (lk == 0) {
                S->cand[rlo][w]     = blo;
                S->cand[rlo + 8][w] = bhi;
            }
        }
        __syncthreads();

        // ---- per-row approx best -> rescue threshold ----
        if (tid < TILE_M) {
            unsigned long long m = S->cand[tid][0];
            #pragma unroll
            for (int w2 = 1; w2 < 8; w2++) {
                unsigned long long o = S->cand[tid][w2];
                if (o < m) m = o;
            }
            S->thr[tid]   = __uint_as_float((uint32_t)(m >> 32)) + MARGIN;
            S->rbest[tid] = ~0ull;
        }
        __syncthreads();

        // ---- stage 2: rescue near-ties with exact R1 chain ----
        #pragma unroll
        for (int mi = 0; mi < 8; mi++) {
            const int rlo = mi * 16 + lg;
            const int rhi = rlo + 8;
            const float zzlo = S->szz[rlo];
            const float zzhi = S->szz[rhi];
            const float tlo = S->thr[rlo];
            const float thi = S->thr[rhi];
            #pragma unroll
            for (int ni = 0; ni < 4; ni++) {
                const int j0 = wN + ni * 8 + lk * 2;
                const float e0 = S->ee[j0];
                const float e1 = S->ee[j0 + 1];
                const float d00 = fmaf(acc[mi][ni][0], -DSCALE, zzlo + e0);
                const float d01 = fmaf(acc[mi][ni][1], -DSCALE, zzlo + e1);
                const float d10 = fmaf(acc[mi][ni][2], -DSCALE, zzhi + e0);
                const float d11 = fmaf(acc[mi][ni][3], -DSCALE, zzhi + e1);
                if (d00 <= tlo) {
                    float de = exact_d(S->zt + rlo * ESTR, Wp + (size_t)j0 * D_DIM, zzlo, e0);
                    atomicMin(&S->rbest[rlo], packdj(de, j0));
                }
                if (d01 <= tlo) {
                    float de = exact_d(S->zt + rlo * ESTR, Wp + (size_t)(j0 + 1) * D_DIM, zzlo, e1);
                    atomicMin(&S->rbest[rlo], packdj(de, j0 + 1));
                }
                if (d10 <= thi) {
                    float de = exact_d(S->zt + rhi * ESTR, Wp + (size_t)j0 * D_DIM, zzhi, e0);
                    atomicMin(&S->rbest[rhi], packdj(de, j0));
                }
                if (d11 <= thi) {
                    float de = exact_d(S->zt + rhi * ESTR, Wp + (size_t)(j0 + 1) * D_DIM, zzhi, e1);
                    atomicMin(&S->rbest[rhi], packdj(de, j0 + 1));
                }
            }
        }
        __syncthreads();

        // ---- commit: exact winner per row ----
        if (tid < TILE_M) {
            const unsigned long long m = S->rbest[tid];
            const int j = (int)(m & 0xffffffffu);
            const float sc = __uint_as_float((uint32_t)(m >> 32));
            S->sidx[tid] = j;
            atomicAdd(&S->shist[j], 1);
            sse_loc += sc;                       // exact ||z - e||^2 (R1 chain)
            out[IDX_OFF + m0 + tid] = (float)j;
        }
        __syncthreads();

        // ---- z_q transposed write (coalesced over t) ----
        {
            const int t = tid & 127, dh = tid >> 7;
            const int n = m0 + t;
            const int b = n >> 14, tt = n & (T_LEN - 1);
            const int j = S->sidx[t];
            const float* er = Wp + (size_t)j * D_DIM;
            float* ob = out + (size_t)b * D_DIM * T_LEN + tt;
            #pragma unroll
            for (int d0 = dh; d0 < D_DIM; d0 += 2)
                ob[(size_t)d0 * T_LEN] = er[d0];
        }
        __syncthreads();
    }

    // ---- block reductions ----
    float s = sse_loc;
    #pragma unroll
    for (int o = 16; o > 0; o >>= 1)
        s += __shfl_down_sync(0xffffffffu, s, o);
    if ((tid & 31) == 0) S->sred[tid >> 5] = s;
    __syncthreads();
    if (tid == 0) {
        float tot = 0.f;
        #pragma unroll
        for (int q = 0; q < 8; q++) tot += S->sred[q];
        atomicAdd(&g_sse, (double)tot);
    }
    atomicAdd(&g_counts[tid], S->shist[tid]);
}

// ------------------------------------------------------------------
__global__ void vq_finalize(float* __restrict__ out) {
    __shared__ float sw[8];
    int tid = threadIdx.x;          // 256 threads
    float c = (float)g_counts[tid];
    g_counts[tid] = 0;              // restore zero-invariant for replay
    float em = c * (1.0f / 262144.0f);
    float v = em * logf(em + 1e-10f);
    #pragma unroll
    for (int o = 16; o > 0; o >>= 1)
        v += __shfl_down_sync(0xffffffffu, v, o);
    if ((tid & 31) == 0) sw[tid >> 5] = v;
    __syncthreads();
    if (tid == 0) {
        float H = 0.f;
        #pragma unroll
        for (int q = 0; q < 8; q++) H += sw[q];
        out[PERP_OFF] = expf(-H);
        double sse = g_sse;
        g_sse = 0.0;                // restore zero-invariant
        float m = (float)(sse * (1.0 / 16777216.0));
        out[LOSS_OFF] = 0.25f * m + m;   // BETA*mse + mse
    }
}

// ------------------------------------------------------------------
extern "C" void kernel_launch(void* const* d_in, const int* in_sizes, int n_in,
                              void* d_out, int out_size) {
    const float* z       = (const float*)d_in[0];
    const float* one_hot = (const float*)d_in[1];
    const float* W       = (const float*)d_in[2];
    float* out           = (float*)d_out;

    int nsm = 148;
    cudaDeviceGetAttribute(&nsm, cudaDevAttrMultiProcessorCount, 0);
    if (nsm <= 0) nsm = 148;

    cudaFuncSetAttribute(vq_mma, cudaFuncAttributeMaxDynamicSharedMemorySize,
                         SMEM_TOT);
    vq_mma<<<nsm, 256, SMEM_TOT>>>(z, one_hot, W, out);
    vq_finalize<<<1, 256>>>(out);
}